// round 1
// baseline (speedup 1.0000x reference)
#include <cuda_runtime.h>

#define NND 20000
#define NE  640000
#define NG  256
#define HD  128
#define ED  64
#define GD  64
#define HID 128

// ---------------- scratch (static device allocations) ----------------
__device__ float d_m[(size_t)NE * HID];       // edge messages m  [E,128]
__device__ float d_matt[NE];
__device__ float d_eatt[NE];
__device__ float d_gmap[NG * HID];
__device__ float d_nmax[NND];
__device__ float d_nsum[NND];
__device__ float d_maggr[(size_t)NND * HID];
__device__ float d_hatt[NND];
__device__ float d_gmaxh[NG];
__device__ float d_gsumh[NG];
__device__ float d_gmaxe[NG];
__device__ float d_gsume[NG];
__device__ float d_haggr[NG * HID];
__device__ float d_eaggr[NG * ED];

__device__ __forceinline__ void atomicMaxF(float* addr, float v) {
    if (v >= 0.f) atomicMax((int*)addr, __float_as_int(v));
    else          atomicMin((unsigned int*)addr, (unsigned int)__float_as_int(v));
}

// ---------------- init ----------------
__global__ void k_init() {
    int i  = blockIdx.x * blockDim.x + threadIdx.x;
    int st = gridDim.x * blockDim.x;
    const float ninf = __int_as_float(0xff800000);
    for (int j = i; j < NND; j += st) { d_nmax[j] = ninf; d_nsum[j] = 0.f; }
    for (int j = i; j < NND * HID; j += st) d_maggr[j] = 0.f;
    for (int j = i; j < NG; j += st) {
        d_gmaxh[j] = ninf; d_gsumh[j] = 0.f;
        d_gmaxe[j] = ninf; d_gsume[j] = 0.f;
    }
    for (int j = i; j < NG * HID; j += st) d_haggr[j] = 0.f;
    for (int j = i; j < NG * ED;  j += st) d_eaggr[j] = 0.f;
}

// ---------------- g_map = g @ Wmap + bmap ----------------
__global__ void k_gmap(const float* __restrict__ g, const float* __restrict__ Wmap,
                       const float* __restrict__ bmap) {
    int r = blockIdx.x, c = threadIdx.x;   // 256 blocks x 128 threads
    __shared__ float sg[GD];
    if (c < GD) sg[c] = g[r * GD + c];
    __syncthreads();
    float s = bmap[c];
#pragma unroll
    for (int k = 0; k < GD; k++) s += sg[k] * Wmap[k * HID + c];
    d_gmap[r * HID + c] = s;
}

// ---------------- h attention logits + per-graph max ----------------
__global__ void k_hatt(const float* __restrict__ h, const int* __restrict__ batch,
                       const float* __restrict__ Wha, const float* __restrict__ bhaP) {
    int w = (blockIdx.x * blockDim.x + threadIdx.x) >> 5;
    int lane = threadIdx.x & 31;
    if (w >= NND) return;
    float4 hv = *(const float4*)(h + (size_t)w * HD + lane * 4);
    float4 wv = *(const float4*)(Wha + lane * 4);
    float s = hv.x * wv.x + hv.y * wv.y + hv.z * wv.z + hv.w * wv.w;
#pragma unroll
    for (int off = 16; off; off >>= 1) s += __shfl_xor_sync(0xffffffffu, s, off);
    if (lane == 0) {
        float att = s + bhaP[0];
        d_hatt[w] = att;
        atomicMaxF(&d_gmaxh[batch[w]], att);
    }
}

// ---------------- fused edge kernel ----------------
// 128 edges per block, 256 threads (16x16), 8x8 / 8x4 register microtiles.
#define LDR 132
__global__ __launch_bounds__(256, 1) void k_edge(
    const float* __restrict__ h, const float* __restrict__ e,
    const int* __restrict__ eidx, const int* __restrict__ batch,
    const float* __restrict__ Wm1, const float* __restrict__ bm1,
    const float* __restrict__ Wm2, const float* __restrict__ bm2,
    const float* __restrict__ Wma, const float* __restrict__ bmaP,
    const float* __restrict__ We1, const float* __restrict__ be1,
    const float* __restrict__ We2, const float* __restrict__ be2,
    const float* __restrict__ Wea, const float* __restrict__ beaP,
    float* __restrict__ eout)
{
    extern __shared__ float smp[];
    float* sX   = smp;                   // 128*LDR : X then Y=m+gmap, [k][row]
    float* sE   = sX + 128 * LDR;        // 64*LDR  : e tile transposed [k][row]
    float* sU   = sE + 64 * LDR;         // 64*LDR  : e-MLP layer1 out [k][row]
    float* sAs  = sU + 64 * LDR;         // 8*LDR
    float* sBs  = sAs + 8 * LDR;         // 8*128
    float* sWma = sBs + 8 * 128;         // 128
    int* sDst = (int*)(sWma + 128);
    int* sSrc = sDst + 128;
    int* sBat = sSrc + 128;

    const int tid = threadIdx.x;
    const int tx = tid & 15, ty = tid >> 4;
    const int e0 = blockIdx.x * 128;

    if (tid < 128) {
        int d = eidx[NE + e0 + tid];
        sDst[tid] = d;
        sSrc[tid] = eidx[e0 + tid];
        sBat[tid] = batch[d];
        sWma[tid] = Wma[tid];
    }
    for (int i = tid; i < 128 * 16; i += 256) {   // e tile -> sE transposed
        int row = i >> 4, c4 = (i & 15) << 2;
        float4 v = *(const float4*)(e + (size_t)(e0 + row) * ED + c4);
        sE[(c4 + 0) * LDR + row] = v.x;
        sE[(c4 + 1) * LDR + row] = v.y;
        sE[(c4 + 2) * LDR + row] = v.z;
        sE[(c4 + 3) * LDR + row] = v.w;
    }
    __syncthreads();

    // ===== GEMM1: [128,320] @ Wm1 -> X = relu(. + bm1)
    float acc[8][8];
#pragma unroll
    for (int i = 0; i < 8; i++)
#pragma unroll
        for (int j = 0; j < 8; j++) acc[i][j] = 0.f;

    for (int kt = 0; kt < 320; kt += 8) {
        __syncthreads();
        const float* A;
        if (kt < 256) {
            int row = tid >> 1;
            int kq = (tid & 1) << 2;
            int kg = kt + kq;
            const float* src = (kg < 128) ? (h + (size_t)sDst[row] * HD + kg)
                                          : (h + (size_t)sSrc[row] * HD + (kg - 128));
            float4 v = *(const float4*)src;
            sAs[(kq + 0) * LDR + row] = v.x;
            sAs[(kq + 1) * LDR + row] = v.y;
            sAs[(kq + 2) * LDR + row] = v.z;
            sAs[(kq + 3) * LDR + row] = v.w;
            A = sAs;
        } else {
            A = sE + (kt - 256) * LDR;
        }
        {
            int k = tid >> 5, c = (tid & 31) << 2;
            *(float4*)(sBs + k * 128 + c) = *(const float4*)(Wm1 + (size_t)(kt + k) * HID + c);
        }
        __syncthreads();
#pragma unroll
        for (int k = 0; k < 8; k++) {
            float4 a0 = *(const float4*)(A + k * LDR + ty * 8);
            float4 a1 = *(const float4*)(A + k * LDR + ty * 8 + 4);
            float4 b0 = *(const float4*)(sBs + k * 128 + tx * 8);
            float4 b1 = *(const float4*)(sBs + k * 128 + tx * 8 + 4);
            float a[8] = {a0.x, a0.y, a0.z, a0.w, a1.x, a1.y, a1.z, a1.w};
            float b[8] = {b0.x, b0.y, b0.z, b0.w, b1.x, b1.y, b1.z, b1.w};
#pragma unroll
            for (int i = 0; i < 8; i++)
#pragma unroll
                for (int j = 0; j < 8; j++) acc[i][j] += a[i] * b[j];
        }
    }
#pragma unroll
    for (int j = 0; j < 8; j++) {
        float bj = bm1[tx * 8 + j];
#pragma unroll
        for (int i = 0; i < 8; i++)
            sX[(tx * 8 + j) * LDR + ty * 8 + i] = fmaxf(acc[i][j] + bj, 0.f);
    }
    __syncthreads();

    // ===== GEMM2: X @ Wm2 -> m = relu(. + bm2)
    float m_[8][8];
#pragma unroll
    for (int i = 0; i < 8; i++)
#pragma unroll
        for (int j = 0; j < 8; j++) m_[i][j] = 0.f;

    for (int kt = 0; kt < 128; kt += 8) {
        __syncthreads();
        {
            int k = tid >> 5, c = (tid & 31) << 2;
            *(float4*)(sBs + k * 128 + c) = *(const float4*)(Wm2 + (size_t)(kt + k) * HID + c);
        }
        __syncthreads();
#pragma unroll
        for (int k = 0; k < 8; k++) {
            const float* A = sX + (kt + k) * LDR;
            float4 a0 = *(const float4*)(A + ty * 8);
            float4 a1 = *(const float4*)(A + ty * 8 + 4);
            float4 b0 = *(const float4*)(sBs + k * 128 + tx * 8);
            float4 b1 = *(const float4*)(sBs + k * 128 + tx * 8 + 4);
            float a[8] = {a0.x, a0.y, a0.z, a0.w, a1.x, a1.y, a1.z, a1.w};
            float b[8] = {b0.x, b0.y, b0.z, b0.w, b1.x, b1.y, b1.z, b1.w};
#pragma unroll
            for (int i = 0; i < 8; i++)
#pragma unroll
                for (int j = 0; j < 8; j++) m_[i][j] += a[i] * b[j];
        }
    }
#pragma unroll
    for (int j = 0; j < 8; j++) {
        float bj = bm2[tx * 8 + j];
#pragma unroll
        for (int i = 0; i < 8; i++) m_[i][j] = fmaxf(m_[i][j] + bj, 0.f);
    }

    // write m to global scratch
#pragma unroll
    for (int i = 0; i < 8; i++) {
        size_t base = (size_t)(e0 + ty * 8 + i) * HID + tx * 8;
        *(float4*)(d_m + base)     = make_float4(m_[i][0], m_[i][1], m_[i][2], m_[i][3]);
        *(float4*)(d_m + base + 4) = make_float4(m_[i][4], m_[i][5], m_[i][6], m_[i][7]);
    }

    // m attention logit + per-node max
    {
        float bma = bmaP[0];
        float part[8];
#pragma unroll
        for (int i = 0; i < 8; i++) {
            float s = 0.f;
#pragma unroll
            for (int j = 0; j < 8; j++) s += m_[i][j] * sWma[tx * 8 + j];
            part[i] = s;
        }
#pragma unroll
        for (int off = 8; off >= 1; off >>= 1)
#pragma unroll
            for (int i = 0; i < 8; i++)
                part[i] += __shfl_xor_sync(0xffffffffu, part[i], off);
        if (tx == 0) {
#pragma unroll
            for (int i = 0; i < 8; i++) {
                int row = ty * 8 + i;
                float att = part[i] + bma;
                d_matt[e0 + row] = att;
                atomicMaxF(&d_nmax[sDst[row]], att);
            }
        }
    }

    // Y = m + g_map[batch[dst]] overwrites sX
    __syncthreads();
#pragma unroll
    for (int i = 0; i < 8; i++) {
        int row = ty * 8 + i;
        const float* gm = d_gmap + (size_t)sBat[row] * HID;
#pragma unroll
        for (int j = 0; j < 8; j++)
            sX[(tx * 8 + j) * LDR + row] = m_[i][j] + gm[tx * 8 + j];
    }

    // e attention logit + per-graph max (reads only sE)
    if (tid < 128) {
        float s = beaP[0];
#pragma unroll
        for (int k = 0; k < ED; k++) s += sE[k * LDR + tid] * Wea[k];
        d_eatt[e0 + tid] = s;
        atomicMaxF(&d_gmaxe[sBat[tid]], s);
    }
    __syncthreads();

    // ===== GEMM3: [e | Y] (192) @ We1 -> relu -> sU
    float a3[8][4];
#pragma unroll
    for (int i = 0; i < 8; i++)
#pragma unroll
        for (int j = 0; j < 4; j++) a3[i][j] = 0.f;

    for (int kt = 0; kt < 192; kt += 8) {
        __syncthreads();
        if (tid < 128) {
            int k = tid >> 4, c = (tid & 15) << 2;
            *(float4*)(sBs + k * 64 + c) = *(const float4*)(We1 + (size_t)(kt + k) * ED + c);
        }
        __syncthreads();
        const float* A = (kt < 64) ? (sE + kt * LDR) : (sX + (kt - 64) * LDR);
#pragma unroll
        for (int k = 0; k < 8; k++) {
            float4 a0 = *(const float4*)(A + k * LDR + ty * 8);
            float4 a1 = *(const float4*)(A + k * LDR + ty * 8 + 4);
            float4 bv = *(const float4*)(sBs + k * 64 + tx * 4);
            float a[8] = {a0.x, a0.y, a0.z, a0.w, a1.x, a1.y, a1.z, a1.w};
            float b[4] = {bv.x, bv.y, bv.z, bv.w};
#pragma unroll
            for (int i = 0; i < 8; i++)
#pragma unroll
                for (int j = 0; j < 4; j++) a3[i][j] += a[i] * b[j];
        }
    }
#pragma unroll
    for (int j = 0; j < 4; j++) {
        float bj = be1[tx * 4 + j];
#pragma unroll
        for (int i = 0; i < 8; i++)
            sU[(tx * 4 + j) * LDR + ty * 8 + i] = fmaxf(a3[i][j] + bj, 0.f);
    }
    __syncthreads();

    // ===== GEMM4: sU @ We2 + be2 ; e_out = relu(e + upd)
    float a4[8][4];
#pragma unroll
    for (int i = 0; i < 8; i++)
#pragma unroll
        for (int j = 0; j < 4; j++) a4[i][j] = 0.f;

    for (int kt = 0; kt < 64; kt += 8) {
        __syncthreads();
        if (tid < 128) {
            int k = tid >> 4, c = (tid & 15) << 2;
            *(float4*)(sBs + k * 64 + c) = *(const float4*)(We2 + (size_t)(kt + k) * ED + c);
        }
        __syncthreads();
#pragma unroll
        for (int k = 0; k < 8; k++) {
            const float* A = sU + (kt + k) * LDR;
            float4 a0 = *(const float4*)(A + ty * 8);
            float4 a1 = *(const float4*)(A + ty * 8 + 4);
            float4 bv = *(const float4*)(sBs + k * 64 + tx * 4);
            float a[8] = {a0.x, a0.y, a0.z, a0.w, a1.x, a1.y, a1.z, a1.w};
            float b[4] = {bv.x, bv.y, bv.z, bv.w};
#pragma unroll
            for (int i = 0; i < 8; i++)
#pragma unroll
                for (int j = 0; j < 4; j++) a4[i][j] += a[i] * b[j];
        }
    }
#pragma unroll
    for (int i = 0; i < 8; i++) {
        int row = ty * 8 + i;
        float o0 = fmaxf(sE[(tx * 4 + 0) * LDR + row] + a4[i][0] + be2[tx * 4 + 0], 0.f);
        float o1 = fmaxf(sE[(tx * 4 + 1) * LDR + row] + a4[i][1] + be2[tx * 4 + 1], 0.f);
        float o2 = fmaxf(sE[(tx * 4 + 2) * LDR + row] + a4[i][2] + be2[tx * 4 + 2], 0.f);
        float o3 = fmaxf(sE[(tx * 4 + 3) * LDR + row] + a4[i][3] + be2[tx * 4 + 3], 0.f);
        *(float4*)(eout + (size_t)(e0 + row) * ED + tx * 4) = make_float4(o0, o1, o2, o3);
    }
}

// ---------------- edge aggregation: softmax numerators via atomics ----------------
__global__ void k_eaggr(const float* __restrict__ e, const int* __restrict__ eidx,
                        const int* __restrict__ batch) {
    int w = (blockIdx.x * blockDim.x + threadIdx.x) >> 5;  // one warp per edge
    int lane = threadIdx.x & 31;
    if (w >= NE) return;
    int d = eidx[NE + w];
    int b = batch[d];
    float ex  = expf(d_matt[w] - d_nmax[d]);
    float exe = expf(d_eatt[w] - d_gmaxe[b]);
    if (lane == 0) {
        atomicAdd(&d_nsum[d], ex);
        atomicAdd(&d_gsume[b], exe);
    }
    float4 mv = *(const float4*)(d_m + (size_t)w * HID + lane * 4);
    float* dst = d_maggr + (size_t)d * HID + lane * 4;
    atomicAdd(dst + 0, mv.x * ex);
    atomicAdd(dst + 1, mv.y * ex);
    atomicAdd(dst + 2, mv.z * ex);
    atomicAdd(dst + 3, mv.w * ex);
    if (lane < 16) {
        float4 ev = *(const float4*)(e + (size_t)w * ED + lane * 4);
        float* de = d_eaggr + (size_t)b * ED + lane * 4;
        atomicAdd(de + 0, ev.x * exe);
        atomicAdd(de + 1, ev.y * exe);
        atomicAdd(de + 2, ev.z * exe);
        atomicAdd(de + 3, ev.w * exe);
    }
}

// ---------------- node -> graph aggregation ----------------
__global__ void k_naggr(const float* __restrict__ h, const int* __restrict__ batch) {
    int w = (blockIdx.x * blockDim.x + threadIdx.x) >> 5;
    int lane = threadIdx.x & 31;
    if (w >= NND) return;
    int b = batch[w];
    float ex = expf(d_hatt[w] - d_gmaxh[b]);
    if (lane == 0) atomicAdd(&d_gsumh[b], ex);
    float4 hv = *(const float4*)(h + (size_t)w * HD + lane * 4);
    float* dst = d_haggr + (size_t)b * HD + lane * 4;
    atomicAdd(dst + 0, hv.x * ex);
    atomicAdd(dst + 1, hv.y * ex);
    atomicAdd(dst + 2, hv.z * ex);
    atomicAdd(dst + 3, hv.w * ex);
}

// ---------------- node update GEMM ----------------
__global__ __launch_bounds__(256, 1) void k_node(
    const float* __restrict__ h, const int* __restrict__ batch,
    const float* __restrict__ Wh1, const float* __restrict__ bh1,
    const float* __restrict__ Wh2, const float* __restrict__ bh2,
    float* __restrict__ hout)
{
    extern __shared__ float smp[];
    float* sZ   = smp;                 // 128*LDR : z = m_aggr/ns + gmap  [k][row]
    float* sX1  = sZ + 128 * LDR;      // 128*LDR : layer1 out
    float* sAs  = sX1 + 128 * LDR;     // 8*LDR
    float* sBs  = sAs + 8 * LDR;       // 8*128
    float* sInv = sBs + 8 * 128;       // 128
    int* sN  = (int*)(sInv + 128);
    int* sBt = sN + 128;

    int tid = threadIdx.x, tx = tid & 15, ty = tid >> 4;
    int n0 = blockIdx.x * 128;
    if (tid < 128) {
        int n = n0 + tid;
        if (n >= NND) n = NND - 1;
        sN[tid] = n;
        sBt[tid] = batch[n];
        sInv[tid] = 1.f / (d_nsum[n] + 1e-16f);
    }
    __syncthreads();
    for (int i = tid; i < 128 * 32; i += 256) {
        int row = i >> 5, c4 = (i & 31) << 2;
        int n = sN[row];
        float inv = sInv[row];
        const float* gm = d_gmap + (size_t)sBt[row] * HID;
        float4 mv = *(const float4*)(d_maggr + (size_t)n * HID + c4);
        sZ[(c4 + 0) * LDR + row] = mv.x * inv + gm[c4 + 0];
        sZ[(c4 + 1) * LDR + row] = mv.y * inv + gm[c4 + 1];
        sZ[(c4 + 2) * LDR + row] = mv.z * inv + gm[c4 + 2];
        sZ[(c4 + 3) * LDR + row] = mv.w * inv + gm[c4 + 3];
    }

    float acc[8][8];
#pragma unroll
    for (int i = 0; i < 8; i++)
#pragma unroll
        for (int j = 0; j < 8; j++) acc[i][j] = 0.f;

    for (int kt = 0; kt < 256; kt += 8) {
        __syncthreads();
        const float* A;
        if (kt < 128) {
            int row = tid >> 1, kq = (tid & 1) << 2;
            float4 v = *(const float4*)(h + (size_t)sN[row] * HD + kt + kq);
            sAs[(kq + 0) * LDR + row] = v.x;
            sAs[(kq + 1) * LDR + row] = v.y;
            sAs[(kq + 2) * LDR + row] = v.z;
            sAs[(kq + 3) * LDR + row] = v.w;
            A = sAs;
        } else {
            A = sZ + (kt - 128) * LDR;
        }
        {
            int k = tid >> 5, c = (tid & 31) << 2;
            *(float4*)(sBs + k * 128 + c) = *(const float4*)(Wh1 + (size_t)(kt + k) * HID + c);
        }
        __syncthreads();
#pragma unroll
        for (int k = 0; k < 8; k++) {
            float4 a0 = *(const float4*)(A + k * LDR + ty * 8);
            float4 a1 = *(const float4*)(A + k * LDR + ty * 8 + 4);
            float4 b0 = *(const float4*)(sBs + k * 128 + tx * 8);
            float4 b1 = *(const float4*)(sBs + k * 128 + tx * 8 + 4);
            float a[8] = {a0.x, a0.y, a0.z, a0.w, a1.x, a1.y, a1.z, a1.w};
            float b[8] = {b0.x, b0.y, b0.z, b0.w, b1.x, b1.y, b1.z, b1.w};
#pragma unroll
            for (int i = 0; i < 8; i++)
#pragma unroll
                for (int j = 0; j < 8; j++) acc[i][j] += a[i] * b[j];
        }
    }
#pragma unroll
    for (int j = 0; j < 8; j++) {
        float bj = bh1[tx * 8 + j];
#pragma unroll
        for (int i = 0; i < 8; i++)
            sX1[(tx * 8 + j) * LDR + ty * 8 + i] = fmaxf(acc[i][j] + bj, 0.f);
    }
    __syncthreads();

    float a2[8][8];
#pragma unroll
    for (int i = 0; i < 8; i++)
#pragma unroll
        for (int j = 0; j < 8; j++) a2[i][j] = 0.f;

    for (int kt = 0; kt < 128; kt += 8) {
        __syncthreads();
        {
            int k = tid >> 5, c = (tid & 31) << 2;
            *(float4*)(sBs + k * 128 + c) = *(const float4*)(Wh2 + (size_t)(kt + k) * HID + c);
        }
        __syncthreads();
#pragma unroll
        for (int k = 0; k < 8; k++) {
            const float* A = sX1 + (kt + k) * LDR;
            float4 a0 = *(const float4*)(A + ty * 8);
            float4 a1 = *(const float4*)(A + ty * 8 + 4);
            float4 b0 = *(const float4*)(sBs + k * 128 + tx * 8);
            float4 b1 = *(const float4*)(sBs + k * 128 + tx * 8 + 4);
            float a[8] = {a0.x, a0.y, a0.z, a0.w, a1.x, a1.y, a1.z, a1.w};
            float b[8] = {b0.x, b0.y, b0.z, b0.w, b1.x, b1.y, b1.z, b1.w};
#pragma unroll
            for (int i = 0; i < 8; i++)
#pragma unroll
                for (int j = 0; j < 8; j++) a2[i][j] += a[i] * b[j];
        }
    }
#pragma unroll
    for (int i = 0; i < 8; i++) {
        int row = ty * 8 + i;
        int n = n0 + row;
        if (n < NND) {
            float o[8];
#pragma unroll
            for (int j = 0; j < 8; j++) {
                float hv = h[(size_t)n * HD + tx * 8 + j];
                o[j] = fmaxf(hv + a2[i][j] + bh2[tx * 8 + j], 0.f);
            }
            *(float4*)(hout + (size_t)n * HD + tx * 8)     = make_float4(o[0], o[1], o[2], o[3]);
            *(float4*)(hout + (size_t)n * HD + tx * 8 + 4) = make_float4(o[4], o[5], o[6], o[7]);
        }
    }
}

// ---------------- graph update ----------------
__global__ void k_graph(const float* __restrict__ g,
                        const float* __restrict__ Wg1, const float* __restrict__ bg1,
                        const float* __restrict__ Wg2, const float* __restrict__ bg2,
                        float* __restrict__ gout) {
    int r = blockIdx.x, c = threadIdx.x;   // 256 blocks x 64 threads
    __shared__ float sin_[256];
    __shared__ float t_[64];
    float invh = 1.f / (d_gsumh[r] + 1e-16f);
    float inve = 1.f / (d_gsume[r] + 1e-16f);
    sin_[c] = g[r * GD + c];
    for (int i = c; i < HD; i += 64) sin_[GD + i] = d_haggr[r * HD + i] * invh;
    sin_[GD + HD + c] = d_eaggr[r * ED + c] * inve;
    __syncthreads();
    float s = bg1[c];
#pragma unroll 8
    for (int k = 0; k < 256; k++) s += sin_[k] * Wg1[k * GD + c];
    t_[c] = fmaxf(s, 0.f);
    __syncthreads();
    float u = bg2[c];
#pragma unroll
    for (int k = 0; k < 64; k++) u += t_[k] * Wg2[k * GD + c];
    gout[r * GD + c] = fmaxf(g[r * GD + c] + u, 0.f);
}

// ---------------- launcher ----------------
extern "C" void kernel_launch(void* const* d_in, const int* in_sizes, int n_in,
                              void* d_out, int out_size)
{
    const float* h    = (const float*)d_in[0];
    const float* e    = (const float*)d_in[1];
    const float* g    = (const float*)d_in[2];
    const int*   eidx = (const int*)d_in[3];
    const int*   batch= (const int*)d_in[4];
    const float* Wmap = (const float*)d_in[5];  const float* bmap = (const float*)d_in[6];
    const float* Wm1  = (const float*)d_in[7];  const float* bm1  = (const float*)d_in[8];
    const float* Wm2  = (const float*)d_in[9];  const float* bm2  = (const float*)d_in[10];
    const float* Wma  = (const float*)d_in[11]; const float* bma  = (const float*)d_in[12];
    const float* Wh1  = (const float*)d_in[13]; const float* bh1  = (const float*)d_in[14];
    const float* Wh2  = (const float*)d_in[15]; const float* bh2  = (const float*)d_in[16];
    const float* Wha  = (const float*)d_in[17]; const float* bha  = (const float*)d_in[18];
    const float* We1  = (const float*)d_in[19]; const float* be1  = (const float*)d_in[20];
    const float* We2  = (const float*)d_in[21]; const float* be2  = (const float*)d_in[22];
    const float* Wea  = (const float*)d_in[23]; const float* bea  = (const float*)d_in[24];
    const float* Wg1  = (const float*)d_in[25]; const float* bg1  = (const float*)d_in[26];
    const float* Wg2  = (const float*)d_in[27]; const float* bg2  = (const float*)d_in[28];

    float* out   = (float*)d_out;
    float* out_h = out;
    float* out_e = out + (size_t)NND * HD;
    float* out_g = out + (size_t)NND * HD + (size_t)NE * ED;

    const int SMEM_EDGE = (128 * LDR + 64 * LDR + 64 * LDR + 8 * LDR + 8 * 128 + 128) * 4 + 3 * 128 * 4;
    const int SMEM_NODE = (128 * LDR + 128 * LDR + 8 * LDR + 8 * 128 + 128) * 4 + 2 * 128 * 4;

    cudaFuncSetAttribute(k_edge, cudaFuncAttributeMaxDynamicSharedMemorySize, SMEM_EDGE);
    cudaFuncSetAttribute(k_node, cudaFuncAttributeMaxDynamicSharedMemorySize, SMEM_NODE);

    k_init<<<512, 256>>>();
    k_gmap<<<NG, 128>>>(g, Wmap, bmap);
    k_hatt<<<(NND * 32 + 255) / 256, 256>>>(h, batch, Wha, bha);
    k_edge<<<NE / 128, 256, SMEM_EDGE>>>(h, e, eidx, batch,
                                         Wm1, bm1, Wm2, bm2, Wma, bma,
                                         We1, be1, We2, be2, Wea, bea, out_e);
    k_eaggr<<<(NE * 32) / 256, 256>>>(e, eidx, batch);
    k_naggr<<<(NND * 32 + 255) / 256, 256>>>(h, batch);
    k_node<<<(NND + 127) / 128, 256, SMEM_NODE>>>(h, batch, Wh1, bh1, Wh2, bh2, out_h);
    k_graph<<<NG, 64>>>(g, Wg1, bg1, Wg2, bg2, out_g);
}

// round 2
// speedup vs baseline: 2.8429x; 2.8429x over previous
#include <cuda_runtime.h>

#define NND 20000
#define NE  640000
#define NG  256
#define HD  128
#define ED  64
#define GD  64
#define HID 128

// pads (floats). A-operand pads %32==4 -> conflict-free frag loads.
// B-operand pads %32==8 -> conflict-free frag loads.
#define PE  68
#define PX  132
#define PU  68
#define PA  36
#define PB  136
#define PB3 72
#define LDR 132

// ---------------- scratch ----------------
__device__ float d_gmap[NG * HID];
__device__ float d_nsum[NND];
__device__ float d_maggr[(size_t)NND * HID];
__device__ float d_gsumh[NG];
__device__ float d_gsume[NG];
__device__ float d_haggr[NG * HID];
__device__ float d_eaggr[NG * ED];

// ---------------- helpers ----------------
__device__ __forceinline__ unsigned f2tf(float x) {
    unsigned r;
    asm("cvt.rna.tf32.f32 %0, %1;" : "=r"(r) : "f"(x));
    return r;
}
__device__ __forceinline__ void mma8(float* c, const unsigned* a, const unsigned* b) {
    asm volatile(
        "mma.sync.aligned.m16n8k8.row.col.f32.tf32.tf32.f32 "
        "{%0,%1,%2,%3}, {%4,%5,%6,%7}, {%8,%9}, {%0,%1,%2,%3};"
        : "+f"(c[0]), "+f"(c[1]), "+f"(c[2]), "+f"(c[3])
        : "r"(a[0]), "r"(a[1]), "r"(a[2]), "r"(a[3]), "r"(b[0]), "r"(b[1]));
}
__device__ __forceinline__ void cp16(void* s, const void* g) {
    unsigned sa = (unsigned)__cvta_generic_to_shared(s);
    asm volatile("cp.async.cg.shared.global [%0], [%1], 16;" :: "r"(sa), "l"(g));
}
#define CP_COMMIT asm volatile("cp.async.commit_group;")
#define CP_WAIT0  asm volatile("cp.async.wait_group 0;")

// warp-tile GEMM step over one 32-wide k-tile. NT n-tiles of 8 cols.
template <int NT>
__device__ __forceinline__ void gemm_tile(float (*c)[NT][4],
                                          const float* __restrict__ At, int padA, int coff,
                                          const float* __restrict__ Bt, int padB,
                                          int rbase, int cbase, int g, int kq) {
#pragma unroll
    for (int k8 = 0; k8 < 4; k8++) {
        unsigned a[2][4];
#pragma unroll
        for (int mt = 0; mt < 2; mt++) {
            const float* p = At + (rbase + mt * 16 + g) * padA + coff + k8 * 8 + kq;
            a[mt][0] = f2tf(p[0]);
            a[mt][1] = f2tf(p[8 * padA]);
            a[mt][2] = f2tf(p[4]);
            a[mt][3] = f2tf(p[8 * padA + 4]);
        }
        unsigned b[NT][2];
#pragma unroll
        for (int nt = 0; nt < NT; nt++) {
            const float* p = Bt + (k8 * 8 + kq) * padB + cbase + nt * 8 + g;
            b[nt][0] = f2tf(p[0]);
            b[nt][1] = f2tf(p[4 * padB]);
        }
#pragma unroll
        for (int mt = 0; mt < 2; mt++)
#pragma unroll
            for (int nt = 0; nt < NT; nt++) mma8(c[mt][nt], a[mt], b[nt]);
    }
}

// ---------------- init ----------------
__global__ void k_init() {
    int i  = blockIdx.x * blockDim.x + threadIdx.x;
    int st = gridDim.x * blockDim.x;
    for (int j = i; j < NND; j += st) d_nsum[j] = 0.f;
    for (int j = i; j < NND * HID; j += st) d_maggr[j] = 0.f;
    for (int j = i; j < NG; j += st) { d_gsumh[j] = 0.f; d_gsume[j] = 0.f; }
    for (int j = i; j < NG * HID; j += st) d_haggr[j] = 0.f;
    for (int j = i; j < NG * ED;  j += st) d_eaggr[j] = 0.f;
}

// ---------------- g_map ----------------
__global__ void k_gmap(const float* __restrict__ g, const float* __restrict__ Wmap,
                       const float* __restrict__ bmap) {
    int r = blockIdx.x, c = threadIdx.x;
    __shared__ float sg[GD];
    if (c < GD) sg[c] = g[r * GD + c];
    __syncthreads();
    float s = bmap[c];
#pragma unroll
    for (int k = 0; k < GD; k++) s += sg[k] * Wmap[k * HID + c];
    d_gmap[r * HID + c] = s;
}

// ---------------- node->graph: att + weighted aggregation (no max pass) -------
__global__ void k_hagg(const float* __restrict__ h, const int* __restrict__ batch,
                       const float* __restrict__ Wha, const float* __restrict__ bhaP) {
    int w = (blockIdx.x * blockDim.x + threadIdx.x) >> 5;
    int lane = threadIdx.x & 31;
    if (w >= NND) return;
    float4 hv = *(const float4*)(h + (size_t)w * HD + lane * 4);
    float4 wv = *(const float4*)(Wha + lane * 4);
    float s = hv.x * wv.x + hv.y * wv.y + hv.z * wv.z + hv.w * wv.w;
#pragma unroll
    for (int off = 16; off; off >>= 1) s += __shfl_xor_sync(0xffffffffu, s, off);
    int b = batch[w];
    float ew = expf(s + bhaP[0]);
    if (lane == 0) atomicAdd(&d_gsumh[b], ew);
    float* dst = d_haggr + b * HD + lane * 4;
    atomicAdd(dst + 0, hv.x * ew);
    atomicAdd(dst + 1, hv.y * ew);
    atomicAdd(dst + 2, hv.z * ew);
    atomicAdd(dst + 3, hv.w * ew);
}

// ---------------- fused edge kernel (tf32 tensor cores) ----------------
__global__ __launch_bounds__(256, 1) void k_edge(
    const float* __restrict__ h, const float* __restrict__ e,
    const int* __restrict__ eidx, const int* __restrict__ batch,
    const float* __restrict__ Wm1, const float* __restrict__ bm1,
    const float* __restrict__ Wm2, const float* __restrict__ bm2,
    const float* __restrict__ Wma, const float* __restrict__ bmaP,
    const float* __restrict__ We1, const float* __restrict__ be1,
    const float* __restrict__ We2, const float* __restrict__ be2,
    const float* __restrict__ Wea, const float* __restrict__ beaP,
    float* __restrict__ eout)
{
    extern __shared__ float smp[];
    float* sE    = smp;                       // 128*PE
    float* sX    = sE + 128 * PE;             // 128*PX
    float* sU    = sX + 128 * PX;             // 128*PU
    float* sA    = sU + 128 * PU;             // 2*128*PA
    float* sB    = sA + 2 * 128 * PA;         // 2*32*PB
    float* sWma  = sB + 2 * 32 * PB;          // 128
    float* sWea  = sWma + 128;                // 64
    float* sMatt = sWea + 64;                 // 128
    float* sWeat = sMatt + 128;               // 128
    float* sBm1  = sWeat + 128;               // 128
    float* sBm2  = sBm1 + 128;                // 128
    float* sBe1  = sBm2 + 128;                // 64
    float* sBe2  = sBe1 + 64;                 // 64
    int* sDst = (int*)(sBe2 + 64);
    int* sSrc = sDst + 128;
    int* sBat = sSrc + 128;

    const int tid  = threadIdx.x;
    const int lane = tid & 31;
    const int wid  = tid >> 5;
    const int wy   = wid >> 1;        // 0..3  -> rows [wy*32, wy*32+32)
    const int wx   = wid & 1;         // 0..1
    const int g    = lane >> 2;
    const int kq   = lane & 3;
    const int e0   = blockIdx.x * 128;

    // ---- prologue: indices / small vectors ----
    if (tid < 128) {
        int d = eidx[NE + e0 + tid];
        sDst[tid] = d;
        sSrc[tid] = eidx[e0 + tid];
        sBat[tid] = batch[d];
        sWma[tid] = Wma[tid];
        sMatt[tid] = bmaP[0];
        sBm1[tid] = bm1[tid];
        sBm2[tid] = bm2[tid];
    }
    if (tid < 64) { sWea[tid] = Wea[tid]; sBe1[tid] = be1[tid]; sBe2[tid] = be2[tid]; }
    __syncthreads();

    // ---- async stage: sE, A-tile0, B-tile0 ----
#pragma unroll
    for (int i = 0; i < 8; i++) {                     // sE: 128x64 raw
        int c = tid + i * 256;
        int row = c >> 4, q = c & 15;
        cp16(sE + row * PE + q * 4, e + (size_t)(e0 + row) * ED + q * 4);
    }
#pragma unroll
    for (int i = 0; i < 4; i++) {                     // A tile 0 (h[dst], k 0..31)
        int c = tid + i * 256;
        int row = c >> 3, q = c & 7;
        cp16(sA + row * PA + q * 4, h + (size_t)sDst[row] * HD + q * 4);
    }
#pragma unroll
    for (int i = 0; i < 4; i++) {                     // B tile 0 (Wm1 k 0..31)
        int c = tid + i * 256;
        int row = c >> 5, q = c & 31;
        cp16(sB + row * PB + q * 4, Wm1 + (size_t)row * HID + q * 4);
    }
    CP_COMMIT;

    // ================= GEMM1: [128,320] @ Wm1 -> X =================
    float acc[2][8][4];
#pragma unroll
    for (int mt = 0; mt < 2; mt++)
#pragma unroll
        for (int nt = 0; nt < 8; nt++)
#pragma unroll
            for (int i = 0; i < 4; i++) acc[mt][nt][i] = 0.f;

    for (int t = 0; t < 10; t++) {
        CP_WAIT0;
        __syncthreads();
        if (t < 9) {
            int tn = t + 1;
            if (tn < 8) {
                const float* base = (tn < 4) ? h : h;
#pragma unroll
                for (int i = 0; i < 4; i++) {
                    int c = tid + i * 256;
                    int row = c >> 3, q = c & 7;
                    const float* src = (tn < 4)
                        ? h + (size_t)sDst[row] * HD + tn * 32 + q * 4
                        : h + (size_t)sSrc[row] * HD + (tn - 4) * 32 + q * 4;
                    cp16(sA + ((tn & 1) * 128 * PA) + row * PA + q * 4, src);
                }
                (void)base;
            }
#pragma unroll
            for (int i = 0; i < 4; i++) {
                int c = tid + i * 256;
                int row = c >> 5, q = c & 31;
                cp16(sB + ((tn & 1) * 32 * PB) + row * PB + q * 4,
                     Wm1 + (size_t)(tn * 32 + row) * HID + q * 4);
            }
            CP_COMMIT;
        }
        const float* At; int padA, coff;
        if (t < 8) { At = sA + (t & 1) * 128 * PA; padA = PA; coff = 0; }
        else       { At = sE; padA = PE; coff = (t - 8) * 32; }
        gemm_tile<8>(acc, At, padA, coff, sB + (t & 1) * 32 * PB, PB, wy * 32, wx * 64, g, kq);
    }

    // epilogue 1: X = relu(acc + bm1) -> sX (raw fp32)
#pragma unroll
    for (int mt = 0; mt < 2; mt++) {
        int r0 = wy * 32 + mt * 16 + g;
#pragma unroll
        for (int nt = 0; nt < 8; nt++) {
            int col = wx * 64 + nt * 8 + kq * 2;
            float b0 = sBm1[col], b1 = sBm1[col + 1];
            *(float2*)&sX[r0 * PX + col] =
                make_float2(fmaxf(acc[mt][nt][0] + b0, 0.f), fmaxf(acc[mt][nt][1] + b1, 0.f));
            *(float2*)&sX[(r0 + 8) * PX + col] =
                make_float2(fmaxf(acc[mt][nt][2] + b0, 0.f), fmaxf(acc[mt][nt][3] + b1, 0.f));
        }
    }
    __syncthreads();

    // stage GEMM2 B tile0
#pragma unroll
    for (int i = 0; i < 4; i++) {
        int c = tid + i * 256;
        int row = c >> 5, q = c & 31;
        cp16(sB + row * PB + q * 4, Wm2 + (size_t)row * HID + q * 4);
    }
    CP_COMMIT;

    // ================= GEMM2: X @ Wm2 -> m =================
#pragma unroll
    for (int mt = 0; mt < 2; mt++)
#pragma unroll
        for (int nt = 0; nt < 8; nt++)
#pragma unroll
            for (int i = 0; i < 4; i++) acc[mt][nt][i] = 0.f;

    for (int t = 0; t < 4; t++) {
        CP_WAIT0;
        __syncthreads();
        if (t < 3) {
            int tn = t + 1;
#pragma unroll
            for (int i = 0; i < 4; i++) {
                int c = tid + i * 256;
                int row = c >> 5, q = c & 31;
                cp16(sB + ((tn & 1) * 32 * PB) + row * PB + q * 4,
                     Wm2 + (size_t)(tn * 32 + row) * HID + q * 4);
            }
            CP_COMMIT;
        }
        gemm_tile<8>(acc, sX, PX, t * 32, sB + (t & 1) * 32 * PB, PB, wy * 32, wx * 64, g, kq);
    }

    // m = relu(acc + bm2) in regs
#pragma unroll
    for (int mt = 0; mt < 2; mt++)
#pragma unroll
        for (int nt = 0; nt < 8; nt++) {
            int col = wx * 64 + nt * 8 + kq * 2;
            float b0 = sBm2[col], b1 = sBm2[col + 1];
            acc[mt][nt][0] = fmaxf(acc[mt][nt][0] + b0, 0.f);
            acc[mt][nt][1] = fmaxf(acc[mt][nt][1] + b1, 0.f);
            acc[mt][nt][2] = fmaxf(acc[mt][nt][2] + b0, 0.f);
            acc[mt][nt][3] = fmaxf(acc[mt][nt][3] + b1, 0.f);
        }

    // m_att partials -> sMatt (init'd to bma)
    {
        float pa[4] = {0.f, 0.f, 0.f, 0.f};
#pragma unroll
        for (int mt = 0; mt < 2; mt++)
#pragma unroll
            for (int nt = 0; nt < 8; nt++) {
                int col = wx * 64 + nt * 8 + kq * 2;
                float w0 = sWma[col], w1 = sWma[col + 1];
                pa[mt * 2 + 0] += acc[mt][nt][0] * w0 + acc[mt][nt][1] * w1;
                pa[mt * 2 + 1] += acc[mt][nt][2] * w0 + acc[mt][nt][3] * w1;
            }
#pragma unroll
        for (int off = 1; off <= 2; off <<= 1)
#pragma unroll
            for (int i = 0; i < 4; i++) pa[i] += __shfl_xor_sync(0xffffffffu, pa[i], off);
        if (kq == 0) {
            atomicAdd(&sMatt[wy * 32 + g],      pa[0]);
            atomicAdd(&sMatt[wy * 32 + g + 8],  pa[1]);
            atomicAdd(&sMatt[wy * 32 + g + 16], pa[2]);
            atomicAdd(&sMatt[wy * 32 + g + 24], pa[3]);
        }
    }
    __syncthreads();

    // per-row softmax weights (no max-shift; logits are tiny) + edge-att
    if (tid < 128) {
        float w = expf(sMatt[tid]);
        sMatt[tid] = w;
        atomicAdd(&d_nsum[sDst[tid]], w);
        float s = beaP[0];
        const float* ep = sE + tid * PE;
#pragma unroll 8
        for (int k = 0; k < ED; k++) s += ep[k] * sWea[k];
        float we = expf(s);
        sWeat[tid] = we;
        atomicAdd(&d_gsume[sBat[tid]], we);
    }
    // stage GEMM3 B tile0 (We1)
#pragma unroll
    for (int i = 0; i < 2; i++) {
        int c = tid + i * 256;
        int row = c >> 4, q = c & 15;
        cp16(sB + row * PB3 + q * 4, We1 + (size_t)row * ED + q * 4);
    }
    CP_COMMIT;
    __syncthreads();

    // m-aggregation REDs + Y = m + gmap[batch[dst]] -> sX (overwrite)
#pragma unroll
    for (int mt = 0; mt < 2; mt++) {
        int r0 = wy * 32 + mt * 16 + g, r1 = r0 + 8;
        float w0r = sMatt[r0], w1r = sMatt[r1];
        int d0 = sDst[r0], d1 = sDst[r1];
        const float* gm0 = d_gmap + (size_t)sBat[r0] * HID;
        const float* gm1 = d_gmap + (size_t)sBat[r1] * HID;
#pragma unroll
        for (int nt = 0; nt < 8; nt++) {
            int col = wx * 64 + nt * 8 + kq * 2;
            atomicAdd(&d_maggr[(size_t)d0 * HID + col],     acc[mt][nt][0] * w0r);
            atomicAdd(&d_maggr[(size_t)d0 * HID + col + 1], acc[mt][nt][1] * w0r);
            atomicAdd(&d_maggr[(size_t)d1 * HID + col],     acc[mt][nt][2] * w1r);
            atomicAdd(&d_maggr[(size_t)d1 * HID + col + 1], acc[mt][nt][3] * w1r);
            *(float2*)&sX[r0 * PX + col] =
                make_float2(acc[mt][nt][0] + gm0[col], acc[mt][nt][1] + gm0[col + 1]);
            *(float2*)&sX[r1 * PX + col] =
                make_float2(acc[mt][nt][2] + gm1[col], acc[mt][nt][3] + gm1[col + 1]);
        }
    }
    // e->graph aggregation REDs
    {
        int row = tid >> 1, cb = (tid & 1) * 32;
        float we = sWeat[row];
        int b = sBat[row];
        float* dstp = d_eaggr + b * ED + cb;
        const float* ep = sE + row * PE + cb;
#pragma unroll
        for (int j = 0; j < 32; j++) atomicAdd(dstp + j, ep[j] * we);
    }

    // ================= GEMM3: [e | Y] (192) @ We1 -> U =================
    float a3[2][4][4];
#pragma unroll
    for (int mt = 0; mt < 2; mt++)
#pragma unroll
        for (int nt = 0; nt < 4; nt++)
#pragma unroll
            for (int i = 0; i < 4; i++) a3[mt][nt][i] = 0.f;

    for (int t = 0; t < 6; t++) {
        CP_WAIT0;
        __syncthreads();
        if (t < 5) {
            int tn = t + 1;
#pragma unroll
            for (int i = 0; i < 2; i++) {
                int c = tid + i * 256;
                int row = c >> 4, q = c & 15;
                cp16(sB + ((tn & 1) * 32 * PB3) + row * PB3 + q * 4,
                     We1 + (size_t)(tn * 32 + row) * ED + q * 4);
            }
            CP_COMMIT;
        }
        const float* At; int padA, coff;
        if (t < 2) { At = sE; padA = PE; coff = t * 32; }
        else       { At = sX; padA = PX; coff = (t - 2) * 32; }
        gemm_tile<4>(a3, At, padA, coff, sB + (t & 1) * 32 * PB3, PB3, wy * 32, wx * 32, g, kq);
    }

    // epilogue 3: U = relu(a3 + be1) -> sU
#pragma unroll
    for (int mt = 0; mt < 2; mt++) {
        int r0 = wy * 32 + mt * 16 + g;
#pragma unroll
        for (int nt = 0; nt < 4; nt++) {
            int col = wx * 32 + nt * 8 + kq * 2;
            float b0 = sBe1[col], b1 = sBe1[col + 1];
            *(float2*)&sU[r0 * PU + col] =
                make_float2(fmaxf(a3[mt][nt][0] + b0, 0.f), fmaxf(a3[mt][nt][1] + b1, 0.f));
            *(float2*)&sU[(r0 + 8) * PU + col] =
                make_float2(fmaxf(a3[mt][nt][2] + b0, 0.f), fmaxf(a3[mt][nt][3] + b1, 0.f));
        }
    }
    // stage GEMM4 B tile0 (We2)
#pragma unroll
    for (int i = 0; i < 2; i++) {
        int c = tid + i * 256;
        int row = c >> 4, q = c & 15;
        cp16(sB + row * PB3 + q * 4, We2 + (size_t)row * ED + q * 4);
    }
    CP_COMMIT;

    // ================= GEMM4: U @ We2 ; e_out = relu(e + . + be2) =================
#pragma unroll
    for (int mt = 0; mt < 2; mt++)
#pragma unroll
        for (int nt = 0; nt < 4; nt++)
#pragma unroll
            for (int i = 0; i < 4; i++) a3[mt][nt][i] = 0.f;

    for (int t = 0; t < 2; t++) {
        CP_WAIT0;
        __syncthreads();
        if (t < 1) {
#pragma unroll
            for (int i = 0; i < 2; i++) {
                int c = tid + i * 256;
                int row = c >> 4, q = c & 15;
                cp16(sB + (32 * PB3) + row * PB3 + q * 4,
                     We2 + (size_t)(32 + row) * ED + q * 4);
            }
            CP_COMMIT;
        }
        gemm_tile<4>(a3, sU, PU, t * 32, sB + (t & 1) * 32 * PB3, PB3, wy * 32, wx * 32, g, kq);
    }

#pragma unroll
    for (int mt = 0; mt < 2; mt++) {
        int r0 = wy * 32 + mt * 16 + g, r1 = r0 + 8;
#pragma unroll
        for (int nt = 0; nt < 4; nt++) {
            int col = wx * 32 + nt * 8 + kq * 2;
            float b0 = sBe2[col], b1 = sBe2[col + 1];
            float2 e0v = *(const float2*)&sE[r0 * PE + col];
            float2 e1v = *(const float2*)&sE[r1 * PE + col];
            *(float2*)&eout[(size_t)(e0 + r0) * ED + col] =
                make_float2(fmaxf(e0v.x + a3[mt][nt][0] + b0, 0.f),
                            fmaxf(e0v.y + a3[mt][nt][1] + b1, 0.f));
            *(float2*)&eout[(size_t)(e0 + r1) * ED + col] =
                make_float2(fmaxf(e1v.x + a3[mt][nt][2] + b0, 0.f),
                            fmaxf(e1v.y + a3[mt][nt][3] + b1, 0.f));
        }
    }
}

// ---------------- node update GEMM (fp32, unchanged from R1) ----------------
__global__ __launch_bounds__(256, 1) void k_node(
    const float* __restrict__ h, const int* __restrict__ batch,
    const float* __restrict__ Wh1, const float* __restrict__ bh1,
    const float* __restrict__ Wh2, const float* __restrict__ bh2,
    float* __restrict__ hout)
{
    extern __shared__ float smp[];
    float* sZ   = smp;
    float* sX1  = sZ + 128 * LDR;
    float* sAs  = sX1 + 128 * LDR;
    float* sBs  = sAs + 8 * LDR;
    float* sInv = sBs + 8 * 128;
    int* sN  = (int*)(sInv + 128);
    int* sBt = sN + 128;

    int tid = threadIdx.x, tx = tid & 15, ty = tid >> 4;
    int n0 = blockIdx.x * 128;
    if (tid < 128) {
        int n = n0 + tid;
        if (n >= NND) n = NND - 1;
        sN[tid] = n;
        sBt[tid] = batch[n];
        sInv[tid] = 1.f / (d_nsum[n] + 1e-16f);
    }
    __syncthreads();
    for (int i = tid; i < 128 * 32; i += 256) {
        int row = i >> 5, c4 = (i & 31) << 2;
        int n = sN[row];
        float inv = sInv[row];
        const float* gm = d_gmap + (size_t)sBt[row] * HID;
        float4 mv = *(const float4*)(d_maggr + (size_t)n * HID + c4);
        sZ[(c4 + 0) * LDR + row] = mv.x * inv + gm[c4 + 0];
        sZ[(c4 + 1) * LDR + row] = mv.y * inv + gm[c4 + 1];
        sZ[(c4 + 2) * LDR + row] = mv.z * inv + gm[c4 + 2];
        sZ[(c4 + 3) * LDR + row] = mv.w * inv + gm[c4 + 3];
    }

    float acc[8][8];
#pragma unroll
    for (int i = 0; i < 8; i++)
#pragma unroll
        for (int j = 0; j < 8; j++) acc[i][j] = 0.f;

    for (int kt = 0; kt < 256; kt += 8) {
        __syncthreads();
        const float* A;
        if (kt < 128) {
            int row = tid >> 1, kqv = (tid & 1) << 2;
            float4 v = *(const float4*)(h + (size_t)sN[row] * HD + kt + kqv);
            sAs[(kqv + 0) * LDR + row] = v.x;
            sAs[(kqv + 1) * LDR + row] = v.y;
            sAs[(kqv + 2) * LDR + row] = v.z;
            sAs[(kqv + 3) * LDR + row] = v.w;
            A = sAs;
        } else {
            A = sZ + (kt - 128) * LDR;
        }
        {
            int k = tid >> 5, c = (tid & 31) << 2;
            *(float4*)(sBs + k * 128 + c) = *(const float4*)(Wh1 + (size_t)(kt + k) * HID + c);
        }
        __syncthreads();
#pragma unroll
        for (int k = 0; k < 8; k++) {
            float4 a0 = *(const float4*)(A + k * LDR + ty * 8);
            float4 a1 = *(const float4*)(A + k * LDR + ty * 8 + 4);
            float4 b0 = *(const float4*)(sBs + k * 128 + tx * 8);
            float4 b1 = *(const float4*)(sBs + k * 128 + tx * 8 + 4);
            float a[8] = {a0.x, a0.y, a0.z, a0.w, a1.x, a1.y, a1.z, a1.w};
            float b[8] = {b0.x, b0.y, b0.z, b0.w, b1.x, b1.y, b1.z, b1.w};
#pragma unroll
            for (int i = 0; i < 8; i++)
#pragma unroll
                for (int j = 0; j < 8; j++) acc[i][j] += a[i] * b[j];
        }
    }
#pragma unroll
    for (int j = 0; j < 8; j++) {
        float bj = bh1[tx * 8 + j];
#pragma unroll
        for (int i = 0; i < 8; i++)
            sX1[(tx * 8 + j) * LDR + ty * 8 + i] = fmaxf(acc[i][j] + bj, 0.f);
    }
    __syncthreads();

    float a2[8][8];
#pragma unroll
    for (int i = 0; i < 8; i++)
#pragma unroll
        for (int j = 0; j < 8; j++) a2[i][j] = 0.f;

    for (int kt = 0; kt < 128; kt += 8) {
        __syncthreads();
        {
            int k = tid >> 5, c = (tid & 31) << 2;
            *(float4*)(sBs + k * 128 + c) = *(const float4*)(Wh2 + (size_t)(kt + k) * HID + c);
        }
        __syncthreads();
#pragma unroll
        for (int k = 0; k < 8; k++) {
            const float* A = sX1 + (kt + k) * LDR;
            float4 a0 = *(const float4*)(A + ty * 8);
            float4 a1 = *(const float4*)(A + ty * 8 + 4);
            float4 b0 = *(const float4*)(sBs + k * 128 + tx * 8);
            float4 b1 = *(const float4*)(sBs + k * 128 + tx * 8 + 4);
            float a[8] = {a0.x, a0.y, a0.z, a0.w, a1.x, a1.y, a1.z, a1.w};
            float b[8] = {b0.x, b0.y, b0.z, b0.w, b1.x, b1.y, b1.z, b1.w};
#pragma unroll
            for (int i = 0; i < 8; i++)
#pragma unroll
                for (int j = 0; j < 8; j++) a2[i][j] += a[i] * b[j];
        }
    }
#pragma unroll
    for (int i = 0; i < 8; i++) {
        int row = ty * 8 + i;
        int n = n0 + row;
        if (n < NND) {
            float o[8];
#pragma unroll
            for (int j = 0; j < 8; j++) {
                float hv = h[(size_t)n * HD + tx * 8 + j];
                o[j] = fmaxf(hv + a2[i][j] + bh2[tx * 8 + j], 0.f);
            }
            *(float4*)(hout + (size_t)n * HD + tx * 8)     = make_float4(o[0], o[1], o[2], o[3]);
            *(float4*)(hout + (size_t)n * HD + tx * 8 + 4) = make_float4(o[4], o[5], o[6], o[7]);
        }
    }
}

// ---------------- graph update ----------------
__global__ void k_graph(const float* __restrict__ g,
                        const float* __restrict__ Wg1, const float* __restrict__ bg1,
                        const float* __restrict__ Wg2, const float* __restrict__ bg2,
                        float* __restrict__ gout) {
    int r = blockIdx.x, c = threadIdx.x;
    __shared__ float sin_[256];
    __shared__ float t_[64];
    float invh = 1.f / (d_gsumh[r] + 1e-16f);
    float inve = 1.f / (d_gsume[r] + 1e-16f);
    sin_[c] = g[r * GD + c];
    for (int i = c; i < HD; i += 64) sin_[GD + i] = d_haggr[r * HD + i] * invh;
    sin_[GD + HD + c] = d_eaggr[r * ED + c] * inve;
    __syncthreads();
    float s = bg1[c];
#pragma unroll 8
    for (int k = 0; k < 256; k++) s += sin_[k] * Wg1[k * GD + c];
    t_[c] = fmaxf(s, 0.f);
    __syncthreads();
    float u = bg2[c];
#pragma unroll
    for (int k = 0; k < 64; k++) u += t_[k] * Wg2[k * GD + c];
    gout[r * GD + c] = fmaxf(g[r * GD + c] + u, 0.f);
}

// ---------------- launcher ----------------
extern "C" void kernel_launch(void* const* d_in, const int* in_sizes, int n_in,
                              void* d_out, int out_size)
{
    const float* h    = (const float*)d_in[0];
    const float* e    = (const float*)d_in[1];
    const float* g    = (const float*)d_in[2];
    const int*   eidx = (const int*)d_in[3];
    const int*   batch= (const int*)d_in[4];
    const float* Wmap = (const float*)d_in[5];  const float* bmap = (const float*)d_in[6];
    const float* Wm1  = (const float*)d_in[7];  const float* bm1  = (const float*)d_in[8];
    const float* Wm2  = (const float*)d_in[9];  const float* bm2  = (const float*)d_in[10];
    const float* Wma  = (const float*)d_in[11]; const float* bma  = (const float*)d_in[12];
    const float* Wh1  = (const float*)d_in[13]; const float* bh1  = (const float*)d_in[14];
    const float* Wh2  = (const float*)d_in[15]; const float* bh2  = (const float*)d_in[16];
    const float* Wha  = (const float*)d_in[17]; const float* bha  = (const float*)d_in[18];
    const float* We1  = (const float*)d_in[19]; const float* be1  = (const float*)d_in[20];
    const float* We2  = (const float*)d_in[21]; const float* be2  = (const float*)d_in[22];
    const float* Wea  = (const float*)d_in[23]; const float* bea  = (const float*)d_in[24];
    const float* Wg1  = (const float*)d_in[25]; const float* bg1  = (const float*)d_in[26];
    const float* Wg2  = (const float*)d_in[27]; const float* bg2  = (const float*)d_in[28];

    float* out   = (float*)d_out;
    float* out_h = out;
    float* out_e = out + (size_t)NND * HD;
    float* out_g = out + (size_t)NND * HD + (size_t)NE * ED;

    const int SMEM_EDGE =
        (128 * PE + 128 * PX + 128 * PU + 2 * 128 * PA + 2 * 32 * PB +
         128 + 64 + 128 + 128 + 128 + 128 + 64 + 64 + 3 * 128) * 4;
    const int SMEM_NODE = (128 * LDR + 128 * LDR + 8 * LDR + 8 * 128 + 128) * 4 + 2 * 128 * 4;

    cudaFuncSetAttribute(k_edge, cudaFuncAttributeMaxDynamicSharedMemorySize, SMEM_EDGE);
    cudaFuncSetAttribute(k_node, cudaFuncAttributeMaxDynamicSharedMemorySize, SMEM_NODE);

    k_init<<<512, 256>>>();
    k_gmap<<<NG, 128>>>(g, Wmap, bmap);
    k_hagg<<<(NND * 32 + 255) / 256, 256>>>(h, batch, Wha, bha);
    k_edge<<<NE / 128, 256, SMEM_EDGE>>>(h, e, eidx, batch,
                                         Wm1, bm1, Wm2, bm2, Wma, bma,
                                         We1, be1, We2, be2, Wea, bea, out_e);
    k_node<<<(NND + 127) / 128, 256, SMEM_NODE>>>(h, batch, Wh1, bh1, Wh2, bh2, out_h);
    k_graph<<<NG, 64>>>(g, Wg1, bg1, Wg2, bg2, out_g);
}

// round 3
// speedup vs baseline: 3.3045x; 1.1624x over previous
#include <cuda_runtime.h>

#define NND 20000
#define NE  640000
#define NG  256
#define HD  128
#define ED  64
#define GD  64
#define HID 128

#define PE  68
#define PX  132
#define PU  68
#define PA  36
#define PB  136
#define PB3 72
#define LDR 132

// ---------------- scratch ----------------
__device__ float d_gmap[NG * HID];
__device__ float d_nsum[NND];
__device__ float d_maggr[(size_t)NND * HID];
__device__ float d_gsumh[NG];
__device__ float d_gsume[NG];
__device__ float d_haggr[NG * HID];
__device__ float d_eaggr[NG * ED];

// ---------------- helpers ----------------
__device__ __forceinline__ void mma8(float* c, const unsigned* a, const unsigned* b) {
    asm volatile(
        "mma.sync.aligned.m16n8k8.row.col.f32.tf32.tf32.f32 "
        "{%0,%1,%2,%3}, {%4,%5,%6,%7}, {%8,%9}, {%0,%1,%2,%3};"
        : "+f"(c[0]), "+f"(c[1]), "+f"(c[2]), "+f"(c[3])
        : "r"(a[0]), "r"(a[1]), "r"(a[2]), "r"(a[3]), "r"(b[0]), "r"(b[1]));
}
__device__ __forceinline__ void cp16(void* s, const void* g) {
    unsigned sa = (unsigned)__cvta_generic_to_shared(s);
    asm volatile("cp.async.cg.shared.global [%0], [%1], 16;" :: "r"(sa), "l"(g));
}
#define CP_COMMIT asm volatile("cp.async.commit_group;")
#define CP_WAIT0  asm volatile("cp.async.wait_group 0;")

__device__ __forceinline__ void red4(float* g, float4 v) {
    asm volatile("red.global.add.v4.f32 [%0], {%1,%2,%3,%4};"
                 :: "l"(g), "f"(v.x), "f"(v.y), "f"(v.z), "f"(v.w) : "memory");
}

// warp-tile GEMM step over one 32-wide k-tile. NT n-tiles of 8 cols.
// Raw fp32 bits fed to tf32 MMA (HW truncation).
template <int NT>
__device__ __forceinline__ void gemm_tile(float (*c)[NT][4],
                                          const float* __restrict__ At, int padA, int coff,
                                          const float* __restrict__ Bt, int padB,
                                          int rbase, int cbase, int g, int kq) {
#pragma unroll
    for (int k8 = 0; k8 < 4; k8++) {
        unsigned a[2][4];
#pragma unroll
        for (int mt = 0; mt < 2; mt++) {
            const float* p = At + (rbase + mt * 16 + g) * padA + coff + k8 * 8 + kq;
            a[mt][0] = __float_as_uint(p[0]);
            a[mt][1] = __float_as_uint(p[8 * padA]);
            a[mt][2] = __float_as_uint(p[4]);
            a[mt][3] = __float_as_uint(p[8 * padA + 4]);
        }
        unsigned b[NT][2];
#pragma unroll
        for (int nt = 0; nt < NT; nt++) {
            const float* p = Bt + (k8 * 8 + kq) * padB + cbase + nt * 8 + g;
            b[nt][0] = __float_as_uint(p[0]);
            b[nt][1] = __float_as_uint(p[4 * padB]);
        }
#pragma unroll
        for (int mt = 0; mt < 2; mt++)
#pragma unroll
            for (int nt = 0; nt < NT; nt++) mma8(c[mt][nt], a[mt], b[nt]);
    }
}

// ---------------- init ----------------
__global__ void k_init() {
    int i  = blockIdx.x * blockDim.x + threadIdx.x;
    int st = gridDim.x * blockDim.x;
    for (int j = i; j < NND; j += st) d_nsum[j] = 0.f;
    for (int j = i; j < NND * HID; j += st) d_maggr[j] = 0.f;
    for (int j = i; j < NG; j += st) { d_gsumh[j] = 0.f; d_gsume[j] = 0.f; }
    for (int j = i; j < NG * HID; j += st) d_haggr[j] = 0.f;
    for (int j = i; j < NG * ED;  j += st) d_eaggr[j] = 0.f;
}

// ---------------- g_map ----------------
__global__ void k_gmap(const float* __restrict__ g, const float* __restrict__ Wmap,
                       const float* __restrict__ bmap) {
    int r = blockIdx.x, c = threadIdx.x;
    __shared__ float sg[GD];
    if (c < GD) sg[c] = g[r * GD + c];
    __syncthreads();
    float s = bmap[c];
#pragma unroll
    for (int k = 0; k < GD; k++) s += sg[k] * Wmap[k * HID + c];
    d_gmap[r * HID + c] = s;
}

// ---------------- node->graph: att + weighted aggregation ----------------
__global__ void k_hagg(const float* __restrict__ h, const int* __restrict__ batch,
                       const float* __restrict__ Wha, const float* __restrict__ bhaP) {
    int w = (blockIdx.x * blockDim.x + threadIdx.x) >> 5;
    int lane = threadIdx.x & 31;
    if (w >= NND) return;
    float4 hv = *(const float4*)(h + (size_t)w * HD + lane * 4);
    float4 wv = *(const float4*)(Wha + lane * 4);
    float s = hv.x * wv.x + hv.y * wv.y + hv.z * wv.z + hv.w * wv.w;
#pragma unroll
    for (int off = 16; off; off >>= 1) s += __shfl_xor_sync(0xffffffffu, s, off);
    int b = batch[w];
    float ew = expf(s + bhaP[0]);
    if (lane == 0) atomicAdd(&d_gsumh[b], ew);
    red4(d_haggr + b * HD + lane * 4,
         make_float4(hv.x * ew, hv.y * ew, hv.z * ew, hv.w * ew));
}

// ---------------- fused edge kernel (tf32 tensor cores) ----------------
__global__ __launch_bounds__(256, 1) void k_edge(
    const float* __restrict__ h, const float* __restrict__ e,
    const int* __restrict__ eidx, const int* __restrict__ batch,
    const float* __restrict__ Wm1, const float* __restrict__ bm1,
    const float* __restrict__ Wm2, const float* __restrict__ bm2,
    const float* __restrict__ Wma, const float* __restrict__ bmaP,
    const float* __restrict__ We1, const float* __restrict__ be1,
    const float* __restrict__ We2, const float* __restrict__ be2,
    const float* __restrict__ Wea, const float* __restrict__ beaP,
    float* __restrict__ eout)
{
    extern __shared__ float smp[];
    float* sE    = smp;                       // 128*PE
    float* sX    = sE + 128 * PE;             // 128*PX
    float* sU    = sX + 128 * PX;             // 128*PU
    float* sA    = sU + 128 * PU;             // 2*128*PA
    float* sB    = sA + 2 * 128 * PA;         // 2*32*PB
    float* sWma  = sB + 2 * 32 * PB;          // 128
    float* sWea  = sWma + 128;                // 64
    float* sMatt = sWea + 64;                 // 128
    float* sWeat = sMatt + 128;               // 128
    float* sBm1  = sWeat + 128;               // 128
    float* sBm2  = sBm1 + 128;                // 128
    float* sBe1  = sBm2 + 128;                // 64
    float* sBe2  = sBe1 + 64;                 // 64
    int* sDst = (int*)(sBe2 + 64);
    int* sSrc = sDst + 128;
    int* sBat = sSrc + 128;

    const int tid  = threadIdx.x;
    const int lane = tid & 31;
    const int wid  = tid >> 5;
    const int wy   = wid >> 1;
    const int wx   = wid & 1;
    const int g    = lane >> 2;
    const int kq   = lane & 3;
    const int e0   = blockIdx.x * 128;

    // ---- prologue ----
    if (tid < 128) {
        int d = eidx[NE + e0 + tid];
        sDst[tid] = d;
        sSrc[tid] = eidx[e0 + tid];
        sBat[tid] = batch[d];
        sWma[tid] = Wma[tid];
        sMatt[tid] = bmaP[0];
        sBm1[tid] = bm1[tid];
        sBm2[tid] = bm2[tid];
    }
    if (tid < 64) { sWea[tid] = Wea[tid]; sBe1[tid] = be1[tid]; sBe2[tid] = be2[tid]; }
    __syncthreads();

    // ---- async stage: sE, A-tile0, B-tile0 ----
#pragma unroll
    for (int i = 0; i < 8; i++) {
        int c = tid + i * 256;
        int row = c >> 4, q = c & 15;
        cp16(sE + row * PE + q * 4, e + (size_t)(e0 + row) * ED + q * 4);
    }
#pragma unroll
    for (int i = 0; i < 4; i++) {
        int c = tid + i * 256;
        int row = c >> 3, q = c & 7;
        cp16(sA + row * PA + q * 4, h + (size_t)sDst[row] * HD + q * 4);
    }
#pragma unroll
    for (int i = 0; i < 4; i++) {
        int c = tid + i * 256;
        int row = c >> 5, q = c & 31;
        cp16(sB + row * PB + q * 4, Wm1 + (size_t)row * HID + q * 4);
    }
    CP_COMMIT;

    // ================= GEMM1 =================
    float acc[2][8][4];
#pragma unroll
    for (int mt = 0; mt < 2; mt++)
#pragma unroll
        for (int nt = 0; nt < 8; nt++)
#pragma unroll
            for (int i = 0; i < 4; i++) acc[mt][nt][i] = 0.f;

    for (int t = 0; t < 10; t++) {
        CP_WAIT0;
        __syncthreads();
        if (t < 9) {
            int tn = t + 1;
            if (tn < 8) {
#pragma unroll
                for (int i = 0; i < 4; i++) {
                    int c = tid + i * 256;
                    int row = c >> 3, q = c & 7;
                    const float* src = (tn < 4)
                        ? h + (size_t)sDst[row] * HD + tn * 32 + q * 4
                        : h + (size_t)sSrc[row] * HD + (tn - 4) * 32 + q * 4;
                    cp16(sA + ((tn & 1) * 128 * PA) + row * PA + q * 4, src);
                }
            }
#pragma unroll
            for (int i = 0; i < 4; i++) {
                int c = tid + i * 256;
                int row = c >> 5, q = c & 31;
                cp16(sB + ((tn & 1) * 32 * PB) + row * PB + q * 4,
                     Wm1 + (size_t)(tn * 32 + row) * HID + q * 4);
            }
            CP_COMMIT;
        }
        const float* At; int padA, coff;
        if (t < 8) { At = sA + (t & 1) * 128 * PA; padA = PA; coff = 0; }
        else       { At = sE; padA = PE; coff = (t - 8) * 32; }
        gemm_tile<8>(acc, At, padA, coff, sB + (t & 1) * 32 * PB, PB, wy * 32, wx * 64, g, kq);
    }

    // epilogue 1: X = relu(acc + bm1) -> sX
#pragma unroll
    for (int mt = 0; mt < 2; mt++) {
        int r0 = wy * 32 + mt * 16 + g;
#pragma unroll
        for (int nt = 0; nt < 8; nt++) {
            int col = wx * 64 + nt * 8 + kq * 2;
            float b0 = sBm1[col], b1 = sBm1[col + 1];
            *(float2*)&sX[r0 * PX + col] =
                make_float2(fmaxf(acc[mt][nt][0] + b0, 0.f), fmaxf(acc[mt][nt][1] + b1, 0.f));
            *(float2*)&sX[(r0 + 8) * PX + col] =
                make_float2(fmaxf(acc[mt][nt][2] + b0, 0.f), fmaxf(acc[mt][nt][3] + b1, 0.f));
        }
    }
    __syncthreads();

    // stage GEMM2 B tile0
#pragma unroll
    for (int i = 0; i < 4; i++) {
        int c = tid + i * 256;
        int row = c >> 5, q = c & 31;
        cp16(sB + row * PB + q * 4, Wm2 + (size_t)row * HID + q * 4);
    }
    CP_COMMIT;

    // ================= GEMM2: X @ Wm2 -> m =================
#pragma unroll
    for (int mt = 0; mt < 2; mt++)
#pragma unroll
        for (int nt = 0; nt < 8; nt++)
#pragma unroll
            for (int i = 0; i < 4; i++) acc[mt][nt][i] = 0.f;

    for (int t = 0; t < 4; t++) {
        CP_WAIT0;
        __syncthreads();
        if (t < 3) {
            int tn = t + 1;
#pragma unroll
            for (int i = 0; i < 4; i++) {
                int c = tid + i * 256;
                int row = c >> 5, q = c & 31;
                cp16(sB + ((tn & 1) * 32 * PB) + row * PB + q * 4,
                     Wm2 + (size_t)(tn * 32 + row) * HID + q * 4);
            }
            CP_COMMIT;
        }
        gemm_tile<8>(acc, sX, PX, t * 32, sB + (t & 1) * 32 * PB, PB, wy * 32, wx * 64, g, kq);
    }
    __syncthreads();   // all reads of sX(X) done before overwrite with m

    // epilogue 2: m = relu(acc+bm2) -> sX ; m_att partials
    {
        float pa[4] = {0.f, 0.f, 0.f, 0.f};
#pragma unroll
        for (int mt = 0; mt < 2; mt++) {
            int r0 = wy * 32 + mt * 16 + g;
#pragma unroll
            for (int nt = 0; nt < 8; nt++) {
                int col = wx * 64 + nt * 8 + kq * 2;
                float b0 = sBm2[col], b1 = sBm2[col + 1];
                float v0 = fmaxf(acc[mt][nt][0] + b0, 0.f);
                float v1 = fmaxf(acc[mt][nt][1] + b1, 0.f);
                float v2 = fmaxf(acc[mt][nt][2] + b0, 0.f);
                float v3 = fmaxf(acc[mt][nt][3] + b1, 0.f);
                *(float2*)&sX[r0 * PX + col]       = make_float2(v0, v1);
                *(float2*)&sX[(r0 + 8) * PX + col] = make_float2(v2, v3);
                float w0 = sWma[col], w1 = sWma[col + 1];
                pa[mt * 2 + 0] += v0 * w0 + v1 * w1;
                pa[mt * 2 + 1] += v2 * w0 + v3 * w1;
            }
        }
#pragma unroll
        for (int off = 1; off <= 2; off <<= 1)
#pragma unroll
            for (int i = 0; i < 4; i++) pa[i] += __shfl_xor_sync(0xffffffffu, pa[i], off);
        if (kq == 0) {
            atomicAdd(&sMatt[wy * 32 + g],      pa[0]);
            atomicAdd(&sMatt[wy * 32 + g + 8],  pa[1]);
            atomicAdd(&sMatt[wy * 32 + g + 16], pa[2]);
            atomicAdd(&sMatt[wy * 32 + g + 24], pa[3]);
        }
    }
    __syncthreads();

    // per-row softmax weights + edge-att weights
    if (tid < 128) {
        float w = expf(sMatt[tid]);
        sMatt[tid] = w;
        atomicAdd(&d_nsum[sDst[tid]], w);
        float s = beaP[0];
        const float* ep = sE + tid * PE;
#pragma unroll 8
        for (int k = 0; k < ED; k++) s += ep[k] * sWea[k];
        float we = expf(s);
        sWeat[tid] = we;
        atomicAdd(&d_gsume[sBat[tid]], we);
    }
    // stage GEMM3 B tile0 (We1)
#pragma unroll
    for (int i = 0; i < 2; i++) {
        int c = tid + i * 256;
        int row = c >> 4, q = c & 15;
        cp16(sB + row * PB3 + q * 4, We1 + (size_t)row * ED + q * 4);
    }
    CP_COMMIT;
    __syncthreads();

    // combined pass: weighted v4-REDs (maggr, eaggr) + Y = m + gmap in place
    {
        int row = tid >> 1, half = tid & 1;
        float wgt = sMatt[row];
        float wee = sWeat[row];
        int dnode = sDst[row];
        int b = sBat[row];
        const float* gm = d_gmap + (size_t)b * HID + half * 64;
        float* mrow = sX + row * PX + half * 64;
        float* mg = d_maggr + (size_t)dnode * HID + half * 64;
#pragma unroll
        for (int j = 0; j < 16; j++) {
            float4 mv = *(const float4*)(mrow + j * 4);
            red4(mg + j * 4, make_float4(mv.x * wgt, mv.y * wgt, mv.z * wgt, mv.w * wgt));
            float4 gv = *(const float4*)(gm + j * 4);
            *(float4*)(mrow + j * 4) =
                make_float4(mv.x + gv.x, mv.y + gv.y, mv.z + gv.z, mv.w + gv.w);
        }
        const float* ep2 = sE + row * PE + half * 32;
        float* ea = d_eaggr + (size_t)b * ED + half * 32;
#pragma unroll
        for (int j = 0; j < 8; j++) {
            float4 ev = *(const float4*)(ep2 + j * 4);
            red4(ea + j * 4, make_float4(ev.x * wee, ev.y * wee, ev.z * wee, ev.w * wee));
        }
    }

    // ================= GEMM3: [e | Y] (192) @ We1 -> U =================
    float a3[2][4][4];
#pragma unroll
    for (int mt = 0; mt < 2; mt++)
#pragma unroll
        for (int nt = 0; nt < 4; nt++)
#pragma unroll
            for (int i = 0; i < 4; i++) a3[mt][nt][i] = 0.f;

    for (int t = 0; t < 6; t++) {
        CP_WAIT0;
        __syncthreads();
        if (t < 5) {
            int tn = t + 1;
#pragma unroll
            for (int i = 0; i < 2; i++) {
                int c = tid + i * 256;
                int row = c >> 4, q = c & 15;
                cp16(sB + ((tn & 1) * 32 * PB3) + row * PB3 + q * 4,
                     We1 + (size_t)(tn * 32 + row) * ED + q * 4);
            }
            CP_COMMIT;
        }
        const float* At; int padA, coff;
        if (t < 2) { At = sE; padA = PE; coff = t * 32; }
        else       { At = sX; padA = PX; coff = (t - 2) * 32; }
        gemm_tile<4>(a3, At, padA, coff, sB + (t & 1) * 32 * PB3, PB3, wy * 32, wx * 32, g, kq);
    }

    // epilogue 3: U = relu(a3 + be1) -> sU
#pragma unroll
    for (int mt = 0; mt < 2; mt++) {
        int r0 = wy * 32 + mt * 16 + g;
#pragma unroll
        for (int nt = 0; nt < 4; nt++) {
            int col = wx * 32 + nt * 8 + kq * 2;
            float b0 = sBe1[col], b1 = sBe1[col + 1];
            *(float2*)&sU[r0 * PU + col] =
                make_float2(fmaxf(a3[mt][nt][0] + b0, 0.f), fmaxf(a3[mt][nt][1] + b1, 0.f));
            *(float2*)&sU[(r0 + 8) * PU + col] =
                make_float2(fmaxf(a3[mt][nt][2] + b0, 0.f), fmaxf(a3[mt][nt][3] + b1, 0.f));
        }
    }
    // stage GEMM4 B tile0 (We2)
#pragma unroll
    for (int i = 0; i < 2; i++) {
        int c = tid + i * 256;
        int row = c >> 4, q = c & 15;
        cp16(sB + row * PB3 + q * 4, We2 + (size_t)row * ED + q * 4);
    }
    CP_COMMIT;

    // ================= GEMM4: U @ We2 ; e_out =================
#pragma unroll
    for (int mt = 0; mt < 2; mt++)
#pragma unroll
        for (int nt = 0; nt < 4; nt++)
#pragma unroll
            for (int i = 0; i < 4; i++) a3[mt][nt][i] = 0.f;

    for (int t = 0; t < 2; t++) {
        CP_WAIT0;
        __syncthreads();
        if (t < 1) {
#pragma unroll
            for (int i = 0; i < 2; i++) {
                int c = tid + i * 256;
                int row = c >> 4, q = c & 15;
                cp16(sB + (32 * PB3) + row * PB3 + q * 4,
                     We2 + (size_t)(32 + row) * ED + q * 4);
            }
            CP_COMMIT;
        }
        gemm_tile<4>(a3, sU, PU, t * 32, sB + (t & 1) * 32 * PB3, PB3, wy * 32, wx * 32, g, kq);
    }

#pragma unroll
    for (int mt = 0; mt < 2; mt++) {
        int r0 = wy * 32 + mt * 16 + g, r1 = r0 + 8;
#pragma unroll
        for (int nt = 0; nt < 4; nt++) {
            int col = wx * 32 + nt * 8 + kq * 2;
            float b0 = sBe2[col], b1 = sBe2[col + 1];
            float2 e0v = *(const float2*)&sE[r0 * PE + col];
            float2 e1v = *(const float2*)&sE[r1 * PE + col];
            *(float2*)&eout[(size_t)(e0 + r0) * ED + col] =
                make_float2(fmaxf(e0v.x + a3[mt][nt][0] + b0, 0.f),
                            fmaxf(e0v.y + a3[mt][nt][1] + b1, 0.f));
            *(float2*)&eout[(size_t)(e0 + r1) * ED + col] =
                make_float2(fmaxf(e1v.x + a3[mt][nt][2] + b0, 0.f),
                            fmaxf(e1v.y + a3[mt][nt][3] + b1, 0.f));
        }
    }
}

// ---------------- node update GEMM (fp32) ----------------
__global__ __launch_bounds__(256, 1) void k_node(
    const float* __restrict__ h, const int* __restrict__ batch,
    const float* __restrict__ Wh1, const float* __restrict__ bh1,
    const float* __restrict__ Wh2, const float* __restrict__ bh2,
    float* __restrict__ hout)
{
    extern __shared__ float smp[];
    float* sZ   = smp;
    float* sX1  = sZ + 128 * LDR;
    float* sAs  = sX1 + 128 * LDR;
    float* sBs  = sAs + 8 * LDR;
    float* sInv = sBs + 8 * 128;
    int* sN  = (int*)(sInv + 128);
    int* sBt = sN + 128;

    int tid = threadIdx.x, tx = tid & 15, ty = tid >> 4;
    int n0 = blockIdx.x * 128;
    if (tid < 128) {
        int n = n0 + tid;
        if (n >= NND) n = NND - 1;
        sN[tid] = n;
        sBt[tid] = batch[n];
        sInv[tid] = 1.f / (d_nsum[n] + 1e-16f);
    }
    __syncthreads();
    for (int i = tid; i < 128 * 32; i += 256) {
        int row = i >> 5, c4 = (i & 31) << 2;
        int n = sN[row];
        float inv = sInv[row];
        const float* gm = d_gmap + (size_t)sBt[row] * HID;
        float4 mv = *(const float4*)(d_maggr + (size_t)n * HID + c4);
        sZ[(c4 + 0) * LDR + row] = mv.x * inv + gm[c4 + 0];
        sZ[(c4 + 1) * LDR + row] = mv.y * inv + gm[c4 + 1];
        sZ[(c4 + 2) * LDR + row] = mv.z * inv + gm[c4 + 2];
        sZ[(c4 + 3) * LDR + row] = mv.w * inv + gm[c4 + 3];
    }

    float acc[8][8];
#pragma unroll
    for (int i = 0; i < 8; i++)
#pragma unroll
        for (int j = 0; j < 8; j++) acc[i][j] = 0.f;

    for (int kt = 0; kt < 256; kt += 8) {
        __syncthreads();
        const float* A;
        if (kt < 128) {
            int row = tid >> 1, kqv = (tid & 1) << 2;
            float4 v = *(const float4*)(h + (size_t)sN[row] * HD + kt + kqv);
            sAs[(kqv + 0) * LDR + row] = v.x;
            sAs[(kqv + 1) * LDR + row] = v.y;
            sAs[(kqv + 2) * LDR + row] = v.z;
            sAs[(kqv + 3) * LDR + row] = v.w;
            A = sAs;
        } else {
            A = sZ + (kt - 128) * LDR;
        }
        {
            int k = tid >> 5, c = (tid & 31) << 2;
            *(float4*)(sBs + k * 128 + c) = *(const float4*)(Wh1 + (size_t)(kt + k) * HID + c);
        }
        __syncthreads();
#pragma unroll
        for (int k = 0; k < 8; k++) {
            float4 a0 = *(const float4*)(A + k * LDR + ty * 8);
            float4 a1 = *(const float4*)(A + k * LDR + ty * 8 + 4);
            float4 b0 = *(const float4*)(sBs + k * 128 + tx * 8);
            float4 b1 = *(const float4*)(sBs + k * 128 + tx * 8 + 4);
            float a[8] = {a0.x, a0.y, a0.z, a0.w, a1.x, a1.y, a1.z, a1.w};
            float b[8] = {b0.x, b0.y, b0.z, b0.w, b1.x, b1.y, b1.z, b1.w};
#pragma unroll
            for (int i = 0; i < 8; i++)
#pragma unroll
                for (int j = 0; j < 8; j++) acc[i][j] += a[i] * b[j];
        }
    }
#pragma unroll
    for (int j = 0; j < 8; j++) {
        float bj = bh1[tx * 8 + j];
#pragma unroll
        for (int i = 0; i < 8; i++)
            sX1[(tx * 8 + j) * LDR + ty * 8 + i] = fmaxf(acc[i][j] + bj, 0.f);
    }
    __syncthreads();

    float a2[8][8];
#pragma unroll
    for (int i = 0; i < 8; i++)
#pragma unroll
        for (int j = 0; j < 8; j++) a2[i][j] = 0.f;

    for (int kt = 0; kt < 128; kt += 8) {
        __syncthreads();
        {
            int k = tid >> 5, c = (tid & 31) << 2;
            *(float4*)(sBs + k * 128 + c) = *(const float4*)(Wh2 + (size_t)(kt + k) * HID + c);
        }
        __syncthreads();
#pragma unroll
        for (int k = 0; k < 8; k++) {
            const float* A = sX1 + (kt + k) * LDR;
            float4 a0 = *(const float4*)(A + ty * 8);
            float4 a1 = *(const float4*)(A + ty * 8 + 4);
            float4 b0 = *(const float4*)(sBs + k * 128 + tx * 8);
            float4 b1 = *(const float4*)(sBs + k * 128 + tx * 8 + 4);
            float a[8] = {a0.x, a0.y, a0.z, a0.w, a1.x, a1.y, a1.z, a1.w};
            float b[8] = {b0.x, b0.y, b0.z, b0.w, b1.x, b1.y, b1.z, b1.w};
#pragma unroll
            for (int i = 0; i < 8; i++)
#pragma unroll
                for (int j = 0; j < 8; j++) a2[i][j] += a[i] * b[j];
        }
    }
#pragma unroll
    for (int i = 0; i < 8; i++) {
        int row = ty * 8 + i;
        int n = n0 + row;
        if (n < NND) {
            float o[8];
#pragma unroll
            for (int j = 0; j < 8; j++) {
                float hv = h[(size_t)n * HD + tx * 8 + j];
                o[j] = fmaxf(hv + a2[i][j] + bh2[tx * 8 + j], 0.f);
            }
            *(float4*)(hout + (size_t)n * HD + tx * 8)     = make_float4(o[0], o[1], o[2], o[3]);
            *(float4*)(hout + (size_t)n * HD + tx * 8 + 4) = make_float4(o[4], o[5], o[6], o[7]);
        }
    }
}

// ---------------- graph update ----------------
__global__ void k_graph(const float* __restrict__ g,
                        const float* __restrict__ Wg1, const float* __restrict__ bg1,
                        const float* __restrict__ Wg2, const float* __restrict__ bg2,
                        float* __restrict__ gout) {
    int r = blockIdx.x, c = threadIdx.x;
    __shared__ float sin_[256];
    __shared__ float t_[64];
    float invh = 1.f / (d_gsumh[r] + 1e-16f);
    float inve = 1.f / (d_gsume[r] + 1e-16f);
    sin_[c] = g[r * GD + c];
    for (int i = c; i < HD; i += 64) sin_[GD + i] = d_haggr[r * HD + i] * invh;
    sin_[GD + HD + c] = d_eaggr[r * ED + c] * inve;
    __syncthreads();
    float s = bg1[c];
#pragma unroll 8
    for (int k = 0; k < 256; k++) s += sin_[k] * Wg1[k * GD + c];
    t_[c] = fmaxf(s, 0.f);
    __syncthreads();
    float u = bg2[c];
#pragma unroll
    for (int k = 0; k < 64; k++) u += t_[k] * Wg2[k * GD + c];
    gout[r * GD + c] = fmaxf(g[r * GD + c] + u, 0.f);
}

// ---------------- launcher ----------------
extern "C" void kernel_launch(void* const* d_in, const int* in_sizes, int n_in,
                              void* d_out, int out_size)
{
    const float* h    = (const float*)d_in[0];
    const float* e    = (const float*)d_in[1];
    const float* g    = (const float*)d_in[2];
    const int*   eidx = (const int*)d_in[3];
    const int*   batch= (const int*)d_in[4];
    const float* Wmap = (const float*)d_in[5];  const float* bmap = (const float*)d_in[6];
    const float* Wm1  = (const float*)d_in[7];  const float* bm1  = (const float*)d_in[8];
    const float* Wm2  = (const float*)d_in[9];  const float* bm2  = (const float*)d_in[10];
    const float* Wma  = (const float*)d_in[11]; const float* bma  = (const float*)d_in[12];
    const float* Wh1  = (const float*)d_in[13]; const float* bh1  = (const float*)d_in[14];
    const float* Wh2  = (const float*)d_in[15]; const float* bh2  = (const float*)d_in[16];
    const float* Wha  = (const float*)d_in[17]; const float* bha  = (const float*)d_in[18];
    const float* We1  = (const float*)d_in[19]; const float* be1  = (const float*)d_in[20];
    const float* We2  = (const float*)d_in[21]; const float* be2  = (const float*)d_in[22];
    const float* Wea  = (const float*)d_in[23]; const float* bea  = (const float*)d_in[24];
    const float* Wg1  = (const float*)d_in[25]; const float* bg1  = (const float*)d_in[26];
    const float* Wg2  = (const float*)d_in[27]; const float* bg2  = (const float*)d_in[28];

    float* out   = (float*)d_out;
    float* out_h = out;
    float* out_e = out + (size_t)NND * HD;
    float* out_g = out + (size_t)NND * HD + (size_t)NE * ED;

    const int SMEM_EDGE =
        (128 * PE + 128 * PX + 128 * PU + 2 * 128 * PA + 2 * 32 * PB +
         128 + 64 + 128 + 128 + 128 + 128 + 64 + 64 + 3 * 128) * 4;
    const int SMEM_NODE = (128 * LDR + 128 * LDR + 8 * LDR + 8 * 128 + 128) * 4 + 2 * 128 * 4;

    cudaFuncSetAttribute(k_edge, cudaFuncAttributeMaxDynamicSharedMemorySize, SMEM_EDGE);
    cudaFuncSetAttribute(k_node, cudaFuncAttributeMaxDynamicSharedMemorySize, SMEM_NODE);

    k_init<<<512, 256>>>();
    k_gmap<<<NG, 128>>>(g, Wmap, bmap);
    k_hagg<<<(NND * 32 + 255) / 256, 256>>>(h, batch, Wha, bha);
    k_edge<<<NE / 128, 256, SMEM_EDGE>>>(h, e, eidx, batch,
                                         Wm1, bm1, Wm2, bm2, Wma, bma,
                                         We1, be1, We2, be2, Wea, bea, out_e);
    k_node<<<(NND + 127) / 128, 256, SMEM_NODE>>>(h, batch, Wh1, bh1, Wh2, bh2, out_h);
    k_graph<<<NG, 64>>>(g, Wg1, bg1, Wg2, bg2, out_g);
}